// round 3
// baseline (speedup 1.0000x reference)
#include <cuda_runtime.h>
#include <math.h>

#define NI 64
#define NJ 64
#define NK 8
#define KEFF 7   // k=0 is the 'none' (zero) primitive -> dropped

// Precomputed W[i][k-1][j] = softmax(alphas[i,j,:])[k] * coeffs[i,j,k]
// Layout is k-major-over-j so that consecutive j are contiguous -> f32x2 pairs.
__device__ float g_W[NI * KEFF * NJ];

typedef unsigned long long u64;

__device__ __forceinline__ u64 pk2(float lo, float hi) {
    u64 r; asm("mov.b64 %0, {%1, %2};" : "=l"(r) : "f"(lo), "f"(hi)); return r;
}
__device__ __forceinline__ void fma2(u64& d, u64 a, u64 b) {
    asm("fma.rn.f32x2 %0, %1, %2, %0;" : "+l"(d) : "l"(a), "l"(b));
}

// ---------------------------------------------------------------------------
// Kernel 1: build W (tiny: 64x64 threads)
// ---------------------------------------------------------------------------
__global__ void build_w_kernel(const float* __restrict__ alphas,
                               const float* __restrict__ coeffs) {
    int i = blockIdx.x;   // input index
    int j = threadIdx.x;  // output index
    const float* a = alphas + (size_t)(i * NJ + j) * NK;
    const float* c = coeffs + (size_t)(i * NJ + j) * NK;

    float av[NK];
#pragma unroll
    for (int k = 0; k < NK; ++k) av[k] = a[k];
    float mx = av[0];
#pragma unroll
    for (int k = 1; k < NK; ++k) mx = fmaxf(mx, av[k]);
    float e[NK];
    float s = 0.f;
#pragma unroll
    for (int k = 0; k < NK; ++k) { e[k] = __expf(av[k] - mx); s += e[k]; }
    float inv = 1.0f / s;
#pragma unroll
    for (int k = 1; k < NK; ++k)
        g_W[((size_t)i * KEFF + (k - 1)) * NJ + j] = e[k] * inv * c[k];
}

// ---------------------------------------------------------------------------
// Kernel 2: main. 256 threads/block, 256 batch-rows/block.
// Thread layout: tg = tid>>2 selects a group of 4 consecutive rows,
//                jq = tid&3 selects a 16-wide j tile.
// Accumulators: 4 rows x 8 j-pairs of f32x2 (64 fp32 accs).
// Inner math: packed fma.rn.f32x2 (2 FMAs per issue) — j-pairs come straight
// out of the contiguous W layout; the primitive value is broadcast-packed.
// ---------------------------------------------------------------------------
__global__ __launch_bounds__(256, 2)
void darts_main_kernel(const float* __restrict__ x,
                       float* __restrict__ out) {
    const int tid = threadIdx.x;
    const int tg  = tid >> 2;        // 0..63
    const int jq  = tid & 3;         // 0..3
    const int j0  = jq * 16;
    const int b0  = blockIdx.x * 256 + tg * 4;

    u64 acc[4][8];
#pragma unroll
    for (int r = 0; r < 4; ++r)
#pragma unroll
        for (int q = 0; q < 8; ++q) acc[r][q] = 0ull;

    const float* xr0 = x + (size_t)b0 * NI;

    for (int i4 = 0; i4 < NI; i4 += 4) {
        // Load 4 x-values per row (vectorized). L1 absorbs the 4x jq duplication.
        float4 xv[4];
#pragma unroll
        for (int r = 0; r < 4; ++r)
            xv[r] = *reinterpret_cast<const float4*>(xr0 + (size_t)r * NI + i4);

#pragma unroll
        for (int ii = 0; ii < 4; ++ii) {
            const int i = i4 + ii;
            float p_[4][KEFF];
#pragma unroll
            for (int r = 0; r < 4; ++r) {
                float xs = (ii == 0) ? xv[r].x : (ii == 1) ? xv[r].y
                          : (ii == 2) ? xv[r].z : xv[r].w;
                float x2 = xs * xs;
                p_[r][0] = xs;                       // linear
                p_[r][1] = x2;                       // x^2
                p_[r][2] = x2 * xs;                  // x^3
                p_[r][3] = __expf(xs);               // exp
                p_[r][4] = __logf(xs);               // ln
                p_[r][5] = __fdividef(1.0f, xs);     // reciprocal (MUFU.RCP)
                p_[r][6] = __sinf(xs);               // sin
            }
#pragma unroll
            for (int k = 0; k < KEFF; ++k) {
                u64 pp[4];
#pragma unroll
                for (int r = 0; r < 4; ++r) pp[r] = pk2(p_[r][k], p_[r][k]);

                const ulonglong2* wrow = reinterpret_cast<const ulonglong2*>(
                    g_W + ((size_t)i * KEFF + k) * NJ + j0);
#pragma unroll
                for (int q2 = 0; q2 < 4; ++q2) {
                    ulonglong2 w2 = wrow[q2];     // 4 consecutive j (2 f32x2 pairs)
#pragma unroll
                    for (int r = 0; r < 4; ++r) {
                        fma2(acc[r][2 * q2 + 0], pp[r], w2.x);
                        fma2(acc[r][2 * q2 + 1], pp[r], w2.y);
                    }
                }
            }
        }
    }

    // Store: each f32x2 pair is 2 consecutive j's -> 8B stores, row-major out.
#pragma unroll
    for (int r = 0; r < 4; ++r) {
        float* orow = out + (size_t)(b0 + r) * NJ + j0;
#pragma unroll
        for (int q = 0; q < 8; ++q)
            *reinterpret_cast<u64*>(orow + 2 * q) = acc[r][q];
    }
}

// ---------------------------------------------------------------------------
extern "C" void kernel_launch(void* const* d_in, const int* in_sizes, int n_in,
                              void* d_out, int out_size) {
    const float* x      = (const float*)d_in[0];  // [B, 64]
    const float* alphas = (const float*)d_in[1];  // [64, 64, 8]
    const float* coeffs = (const float*)d_in[2];  // [64, 64, 8]
    float* out = (float*)d_out;                   // [B, 64]

    int rows = in_sizes[0] / NI;                  // 65536

    build_w_kernel<<<NI, NJ>>>(alphas, coeffs);
    darts_main_kernel<<<rows / 256, 256>>>(x, out);
}